// round 9
// baseline (speedup 1.0000x reference)
#include <cuda_runtime.h>
#include <cstdint>

#define DE 128
#define BMAX 8192
#define NMAX 1000000

__device__ float g_qW[BMAX * DE];
__device__ int   g_hist[BMAX];
__device__ int   g_off[BMAX];
__device__ int   g_cur[BMAX];
__device__ int   g_nodes[NMAX];

// ---------------------------------------------------------------- zero hist (must precede hist atomics)
__global__ void k_zero(int B) {
    int i = blockIdx.x * blockDim.x + threadIdx.x;   // 2048 threads of int4
    ((int4*)g_hist)[i] = make_int4(0, 0, 0, 0);
}

// ---------------------------------------------------------------- fused: qW = query @ W  |  histogram
// blocks [0, QB): qw (128 thr, 32 rows/block). blocks [QB, ...): hist, 8 elems/thread.
__global__ void k_qwhist(const float* __restrict__ query, const float* __restrict__ W,
                         const int* __restrict__ index, int B, int N, int QB) {
    int t = threadIdx.x;  // 128 threads
    if ((int)blockIdx.x < QB) {
        __shared__ float qs[32][DE + 4];
        int row0 = blockIdx.x * 32;
        #pragma unroll
        for (int j = 0; j < 32; j++) {
            int r = row0 + j;
            qs[j][t] = (r < B) ? query[r * DE + t] : 0.f;
        }
        __syncthreads();
        float acc[32];
        #pragma unroll
        for (int r = 0; r < 32; r++) acc[r] = 0.f;
        for (int k = 0; k < DE; k++) {
            float w = W[k * DE + t];
            #pragma unroll
            for (int r = 0; r < 32; r++) acc[r] = fmaf(qs[r][k], w, acc[r]);
        }
        #pragma unroll
        for (int r = 0; r < 32; r++) {
            int rr = row0 + r;
            if (rr < B) g_qW[rr * DE + t] = acc[r];
        }
    } else {
        int bid = blockIdx.x - QB;
        int i8 = (bid * 128 + t) * 8;
        if (i8 + 7 < N) {
            int4 a = *(const int4*)(index + i8);
            int4 b = *(const int4*)(index + i8 + 4);
            atomicAdd(&g_hist[a.x], 1);
            atomicAdd(&g_hist[a.y], 1);
            atomicAdd(&g_hist[a.z], 1);
            atomicAdd(&g_hist[a.w], 1);
            atomicAdd(&g_hist[b.x], 1);
            atomicAdd(&g_hist[b.y], 1);
            atomicAdd(&g_hist[b.z], 1);
            atomicAdd(&g_hist[b.w], 1);
        } else {
            for (int j = i8; j < N; j++) atomicAdd(&g_hist[index[j]], 1);
        }
    }
}

// ---------------------------------------------------------------- exclusive scan (256 thr x 32 bins)
__global__ void k_scan(int B) {
    __shared__ int warp_sums[8];
    int t = threadIdx.x;
    int lane = t & 31, w = t >> 5;
    int base = t * 32;
    int loc[32];
    int s = 0;
    const int4* hp = (const int4*)&g_hist[base];
    #pragma unroll
    for (int j = 0; j < 8; j++) {
        int4 v = (base + j * 4 + 3 < B) ? hp[j] : make_int4(0, 0, 0, 0);
        loc[j * 4 + 0] = s; s += v.x;
        loc[j * 4 + 1] = s; s += v.y;
        loc[j * 4 + 2] = s; s += v.z;
        loc[j * 4 + 3] = s; s += v.w;
    }
    int incl = s;
    #pragma unroll
    for (int o = 1; o < 32; o <<= 1) {
        int v = __shfl_up_sync(0xffffffffu, incl, o);
        if (lane >= o) incl += v;
    }
    if (lane == 31) warp_sums[w] = incl;
    __syncthreads();
    int wpre = 0;
    #pragma unroll
    for (int k = 0; k < 8; k++) wpre += (k < w) ? warp_sums[k] : 0;
    int pre = wpre + incl - s;
    int4* op = (int4*)&g_off[base];
    int4* cp = (int4*)&g_cur[base];
    #pragma unroll
    for (int j = 0; j < 8; j++) {
        if (base + j * 4 + 3 < B) {
            int4 o4 = make_int4(pre + loc[j * 4 + 0], pre + loc[j * 4 + 1],
                                pre + loc[j * 4 + 2], pre + loc[j * 4 + 3]);
            op[j] = o4;
            cp[j] = o4;
        }
    }
}

// ---------------------------------------------------------------- scatter node ids (ILP 8)
__global__ void k_scatter(const int* __restrict__ index, int N) {
    int i8 = (blockIdx.x * blockDim.x + threadIdx.x) * 8;
    if (i8 + 7 < N) {
        int4 a = *(const int4*)(index + i8);
        int4 b = *(const int4*)(index + i8 + 4);
        int p0 = atomicAdd(&g_cur[a.x], 1);
        int p1 = atomicAdd(&g_cur[a.y], 1);
        int p2 = atomicAdd(&g_cur[a.z], 1);
        int p3 = atomicAdd(&g_cur[a.w], 1);
        int p4 = atomicAdd(&g_cur[b.x], 1);
        int p5 = atomicAdd(&g_cur[b.y], 1);
        int p6 = atomicAdd(&g_cur[b.z], 1);
        int p7 = atomicAdd(&g_cur[b.w], 1);
        g_nodes[p0] = i8;
        g_nodes[p1] = i8 + 1;
        g_nodes[p2] = i8 + 2;
        g_nodes[p3] = i8 + 3;
        g_nodes[p4] = i8 + 4;
        g_nodes[p5] = i8 + 5;
        g_nodes[p6] = i8 + 6;
        g_nodes[p7] = i8 + 7;
    } else {
        for (int j = i8; j < N; j++) {
            int p = atomicAdd(&g_cur[index[j]], 1);
            g_nodes[p] = j;
        }
    }
}

// ---------------------------------------------------------------- main: single-pass online softmax
// Block per segment. Warp per row (lane holds float4 of the row). Each row of
// `values` is read from DRAM exactly ONCE. Per-warp running (m, ssum, acc) with
// one rescale per 4-row batch; 8-warp split-softmax merge at the end.
__global__ void __launch_bounds__(256) k_main(const float* __restrict__ values,
                                              float* __restrict__ out, int B) {
    __shared__ float sm[8], ssw[8];
    __shared__ float4 part4[8][32];

    int b = blockIdx.x;
    int tid = threadIdx.x, lane = tid & 31, wid = tid >> 5;

    int off = __ldg(&g_off[b]);
    int cnt = __ldg(&g_hist[b]);

    float4 qv = __ldg((const float4*)(g_qW + (size_t)b * DE + lane * 4));

    float m = -3.4e38f, ssum = 0.f;
    float4 acc = make_float4(0.f, 0.f, 0.f, 0.f);
    const float rs = 0.08838834764831845f;   // 1/sqrt(128)

    for (int i0 = wid * 4; i0 < cnt; i0 += 32) {
        float4 v[4];
        float d[4];
        #pragma unroll
        for (int u = 0; u < 4; u++) {
            int ii = i0 + u;
            if (ii < cnt) {
                int nd = __ldg(&g_nodes[off + ii]);
                v[u] = __ldg((const float4*)(values + (size_t)nd * DE + lane * 4));
            } else {
                v[u] = make_float4(0.f, 0.f, 0.f, 0.f);
            }
        }
        #pragma unroll
        for (int u = 0; u < 4; u++)
            d[u] = v[u].x * qv.x + v[u].y * qv.y + v[u].z * qv.z + v[u].w * qv.w;
        #pragma unroll
        for (int o = 16; o > 0; o >>= 1) {
            #pragma unroll
            for (int u = 0; u < 4; u++)
                d[u] += __shfl_xor_sync(0xffffffffu, d[u], o);   // all lanes get the dot
        }
        #pragma unroll
        for (int u = 0; u < 4; u++)
            d[u] = (i0 + u < cnt) ? d[u] * rs : -3.4e38f;

        float mb = fmaxf(fmaxf(d[0], d[1]), fmaxf(d[2], d[3]));
        float mn = fmaxf(m, mb);
        float scale = __expf(m - mn);          // underflows to 0 on first batch
        float e[4];
        #pragma unroll
        for (int u = 0; u < 4; u++) e[u] = __expf(d[u] - mn);   // invalid -> 0
        ssum = fmaf(ssum, scale, (e[0] + e[1]) + (e[2] + e[3]));
        acc.x = fmaf(acc.x, scale, fmaf(e[0], v[0].x, fmaf(e[1], v[1].x, fmaf(e[2], v[2].x, e[3] * v[3].x))));
        acc.y = fmaf(acc.y, scale, fmaf(e[0], v[0].y, fmaf(e[1], v[1].y, fmaf(e[2], v[2].y, e[3] * v[3].y))));
        acc.z = fmaf(acc.z, scale, fmaf(e[0], v[0].z, fmaf(e[1], v[1].z, fmaf(e[2], v[2].z, e[3] * v[3].z))));
        acc.w = fmaf(acc.w, scale, fmaf(e[0], v[0].w, fmaf(e[1], v[1].w, fmaf(e[2], v[2].w, e[3] * v[3].w))));
        m = mn;
    }

    // -------- split-softmax merge across 8 warps
    if (lane == 0) { sm[wid] = m; ssw[wid] = ssum; }
    __syncthreads();

    float mg = sm[0];
    #pragma unroll
    for (int w = 1; w < 8; w++) mg = fmaxf(mg, sm[w]);
    float sg = 0.f;
    #pragma unroll
    for (int w = 0; w < 8; w++) sg += ssw[w] * __expf(sm[w] - mg);
    float myscale = __expf(m - mg);

    part4[wid][lane] = make_float4(acc.x * myscale, acc.y * myscale,
                                   acc.z * myscale, acc.w * myscale);
    __syncthreads();

    if (tid < DE) {
        const float* pf = (const float*)part4;
        float o = 0.f;
        #pragma unroll
        for (int w = 0; w < 8; w++) o += pf[w * DE + tid];
        float inv = (sg > 0.f) ? 1.f / sg : 0.f;
        __stcg(&out[(size_t)b * DE + tid], o * inv);
    }
}

// ---------------------------------------------------------------- launch
extern "C" void kernel_launch(void* const* d_in, const int* in_sizes, int n_in,
                              void* d_out, int out_size) {
    const float* query  = (const float*)d_in[0];
    const float* values = (const float*)d_in[1];
    const int*   index  = (const int*)d_in[2];
    const float* W      = (const float*)d_in[3];
    float* out = (float*)d_out;

    int B = in_sizes[0] / DE;   // 8192
    int N = in_sizes[2];        // 1,000,000

    int QB = (B + 31) / 32;                      // 256 qw blocks
    int HB = (N + 8 * 128 - 1) / (8 * 128);      // hist blocks (8 elems/thread, 128 thr)

    k_zero<<<(B / 4 + 255) / 256, 256>>>(B);
    k_qwhist<<<QB + HB, 128>>>(query, W, index, B, N, QB);
    k_scan<<<1, 256>>>(B);
    k_scatter<<<(N + 8 * 256 - 1) / (8 * 256), 256>>>(index, N);
    k_main<<<B, 256>>>(values, out, B);
}

// round 10
// speedup vs baseline: 1.1127x; 1.1127x over previous
#include <cuda_runtime.h>
#include <cstdint>

#define DE 128
#define BMAX 8192
#define NMAX 1000000

__device__ float g_qW[BMAX * DE];
__device__ int   g_hist[BMAX];
__device__ int   g_off[BMAX];
__device__ int   g_rank[NMAX];
__device__ int   g_nodes[NMAX];

// ---------------------------------------------------------------- zero hist (must precede hist atomics)
__global__ void k_zero(int B) {
    int i = blockIdx.x * blockDim.x + threadIdx.x;   // 2048 threads of int4
    ((int4*)g_hist)[i] = make_int4(0, 0, 0, 0);
}

// ---------------------------------------------------------------- fused: qW = query @ W  |  histogram+rank
// blocks [0, QB): qw (128 thr, 32 rows/block). blocks [QB, ...): hist, 8 elems/thread.
// The atomicAdd return value is the node's rank within its segment -> stored for atomic-free scatter.
__global__ void k_qwhist(const float* __restrict__ query, const float* __restrict__ W,
                         const int* __restrict__ index, int B, int N, int QB) {
    int t = threadIdx.x;  // 128 threads
    if ((int)blockIdx.x < QB) {
        __shared__ float qs[32][DE + 4];
        int row0 = blockIdx.x * 32;
        #pragma unroll
        for (int j = 0; j < 32; j++) {
            int r = row0 + j;
            qs[j][t] = (r < B) ? query[r * DE + t] : 0.f;
        }
        __syncthreads();
        float acc[32];
        #pragma unroll
        for (int r = 0; r < 32; r++) acc[r] = 0.f;
        for (int k = 0; k < DE; k++) {
            float w = W[k * DE + t];
            #pragma unroll
            for (int r = 0; r < 32; r++) acc[r] = fmaf(qs[r][k], w, acc[r]);
        }
        #pragma unroll
        for (int r = 0; r < 32; r++) {
            int rr = row0 + r;
            if (rr < B) g_qW[rr * DE + t] = acc[r];
        }
    } else {
        int bid = blockIdx.x - QB;
        int i8 = (bid * 128 + t) * 8;
        if (i8 + 7 < N) {
            int4 a = *(const int4*)(index + i8);
            int4 b = *(const int4*)(index + i8 + 4);
            int r0 = atomicAdd(&g_hist[a.x], 1);
            int r1 = atomicAdd(&g_hist[a.y], 1);
            int r2 = atomicAdd(&g_hist[a.z], 1);
            int r3 = atomicAdd(&g_hist[a.w], 1);
            int r4 = atomicAdd(&g_hist[b.x], 1);
            int r5 = atomicAdd(&g_hist[b.y], 1);
            int r6 = atomicAdd(&g_hist[b.z], 1);
            int r7 = atomicAdd(&g_hist[b.w], 1);
            *(int4*)(g_rank + i8)     = make_int4(r0, r1, r2, r3);
            *(int4*)(g_rank + i8 + 4) = make_int4(r4, r5, r6, r7);
        } else {
            for (int j = i8; j < N; j++) g_rank[j] = atomicAdd(&g_hist[index[j]], 1);
        }
    }
}

// ---------------------------------------------------------------- exclusive scan (256 thr x 32 bins)
__global__ void k_scan(int B) {
    __shared__ int warp_sums[8];
    int t = threadIdx.x;
    int lane = t & 31, w = t >> 5;
    int base = t * 32;
    int loc[32];
    int s = 0;
    const int4* hp = (const int4*)&g_hist[base];
    #pragma unroll
    for (int j = 0; j < 8; j++) {
        int4 v = (base + j * 4 + 3 < B) ? hp[j] : make_int4(0, 0, 0, 0);
        loc[j * 4 + 0] = s; s += v.x;
        loc[j * 4 + 1] = s; s += v.y;
        loc[j * 4 + 2] = s; s += v.z;
        loc[j * 4 + 3] = s; s += v.w;
    }
    int incl = s;
    #pragma unroll
    for (int o = 1; o < 32; o <<= 1) {
        int v = __shfl_up_sync(0xffffffffu, incl, o);
        if (lane >= o) incl += v;
    }
    if (lane == 31) warp_sums[w] = incl;
    __syncthreads();
    int wpre = 0;
    #pragma unroll
    for (int k = 0; k < 8; k++) wpre += (k < w) ? warp_sums[k] : 0;
    int pre = wpre + incl - s;
    int4* op = (int4*)&g_off[base];
    #pragma unroll
    for (int j = 0; j < 8; j++) {
        if (base + j * 4 + 3 < B) {
            op[j] = make_int4(pre + loc[j * 4 + 0], pre + loc[j * 4 + 1],
                              pre + loc[j * 4 + 2], pre + loc[j * 4 + 3]);
        }
    }
}

// ---------------------------------------------------------------- scatter node ids — ATOMIC-FREE (rank trick)
__global__ void k_scatter(const int* __restrict__ index, int N) {
    int i8 = (blockIdx.x * blockDim.x + threadIdx.x) * 8;
    if (i8 + 7 < N) {
        int4 a = *(const int4*)(index + i8);
        int4 b = *(const int4*)(index + i8 + 4);
        int4 ra = *(const int4*)(g_rank + i8);
        int4 rb = *(const int4*)(g_rank + i8 + 4);
        g_nodes[__ldg(&g_off[a.x]) + ra.x] = i8;
        g_nodes[__ldg(&g_off[a.y]) + ra.y] = i8 + 1;
        g_nodes[__ldg(&g_off[a.z]) + ra.z] = i8 + 2;
        g_nodes[__ldg(&g_off[a.w]) + ra.w] = i8 + 3;
        g_nodes[__ldg(&g_off[b.x]) + rb.x] = i8 + 4;
        g_nodes[__ldg(&g_off[b.y]) + rb.y] = i8 + 5;
        g_nodes[__ldg(&g_off[b.z]) + rb.z] = i8 + 6;
        g_nodes[__ldg(&g_off[b.w]) + rb.w] = i8 + 7;
    } else {
        for (int j = i8; j < N; j++)
            g_nodes[__ldg(&g_off[index[j]]) + g_rank[j]] = j;
    }
}

// ---------------------------------------------------------------- main: single-pass online softmax
// Block per segment, warp per row (lane holds float4). 8 rows in flight per warp.
// Dot consumes v immediately; pooling accumulate RE-LOADS v (L1/L2 hit) to keep regs low.
__global__ void __launch_bounds__(256) k_main(const float* __restrict__ values,
                                              float* __restrict__ out, int B) {
    __shared__ float sm[8], ssw[8];
    __shared__ float4 part4[8][32];

    int b = blockIdx.x;
    int tid = threadIdx.x, lane = tid & 31, wid = tid >> 5;

    int off = __ldg(&g_off[b]);
    int cnt = __ldg(&g_hist[b]);

    float4 qv = __ldg((const float4*)(g_qW + (size_t)b * DE + lane * 4));

    float m = -3.4e38f, ssum = 0.f;
    float4 acc = make_float4(0.f, 0.f, 0.f, 0.f);
    const float rs = 0.08838834764831845f;   // 1/sqrt(128)

    for (int i0 = wid * 8; i0 < cnt; i0 += 64) {
        int nd[8];
        float d[8];
        #pragma unroll
        for (int u = 0; u < 8; u++) {
            int ii = i0 + u;
            nd[u] = (ii < cnt) ? __ldg(&g_nodes[off + ii]) : -1;
        }
        #pragma unroll
        for (int u = 0; u < 8; u++) {
            if (nd[u] >= 0) {
                float4 v = __ldg((const float4*)(values + (size_t)nd[u] * DE + lane * 4));
                d[u] = v.x * qv.x + v.y * qv.y + v.z * qv.z + v.w * qv.w;
            } else {
                d[u] = 0.f;
            }
        }
        #pragma unroll
        for (int o = 16; o > 0; o >>= 1) {
            #pragma unroll
            for (int u = 0; u < 8; u++)
                d[u] += __shfl_xor_sync(0xffffffffu, d[u], o);   // all lanes get each dot
        }
        #pragma unroll
        for (int u = 0; u < 8; u++)
            d[u] = (nd[u] >= 0) ? d[u] * rs : -3.4e38f;

        float mb = fmaxf(fmaxf(fmaxf(d[0], d[1]), fmaxf(d[2], d[3])),
                         fmaxf(fmaxf(d[4], d[5]), fmaxf(d[6], d[7])));
        float mn = fmaxf(m, mb);
        float scale = __expf(m - mn);          // 0 on first batch
        float e[8];
        float eb = 0.f;
        #pragma unroll
        for (int u = 0; u < 8; u++) { e[u] = __expf(d[u] - mn); eb += e[u]; }
        ssum = fmaf(ssum, scale, eb);
        acc.x *= scale; acc.y *= scale; acc.z *= scale; acc.w *= scale;
        #pragma unroll
        for (int u = 0; u < 8; u++) {
            if (nd[u] >= 0) {
                float4 v = __ldg((const float4*)(values + (size_t)nd[u] * DE + lane * 4));
                acc.x = fmaf(e[u], v.x, acc.x);
                acc.y = fmaf(e[u], v.y, acc.y);
                acc.z = fmaf(e[u], v.z, acc.z);
                acc.w = fmaf(e[u], v.w, acc.w);
            }
        }
        m = mn;
    }

    // -------- split-softmax merge across 8 warps
    if (lane == 0) { sm[wid] = m; ssw[wid] = ssum; }
    __syncthreads();

    float mg = sm[0];
    #pragma unroll
    for (int w = 1; w < 8; w++) mg = fmaxf(mg, sm[w]);
    float sg = 0.f;
    #pragma unroll
    for (int w = 0; w < 8; w++) sg += ssw[w] * __expf(sm[w] - mg);
    float myscale = __expf(m - mg);

    part4[wid][lane] = make_float4(acc.x * myscale, acc.y * myscale,
                                   acc.z * myscale, acc.w * myscale);
    __syncthreads();

    if (tid < DE) {
        const float* pf = (const float*)part4;
        float o = 0.f;
        #pragma unroll
        for (int w = 0; w < 8; w++) o += pf[w * DE + tid];
        float inv = (sg > 0.f) ? 1.f / sg : 0.f;
        __stcg(&out[(size_t)b * DE + tid], o * inv);
    }
}

// ---------------------------------------------------------------- launch
extern "C" void kernel_launch(void* const* d_in, const int* in_sizes, int n_in,
                              void* d_out, int out_size) {
    const float* query  = (const float*)d_in[0];
    const float* values = (const float*)d_in[1];
    const int*   index  = (const int*)d_in[2];
    const float* W      = (const float*)d_in[3];
    float* out = (float*)d_out;

    int B = in_sizes[0] / DE;   // 8192
    int N = in_sizes[2];        // 1,000,000

    int QB = (B + 31) / 32;                      // 256 qw blocks
    int HB = (N + 8 * 128 - 1) / (8 * 128);      // hist blocks (8 elems/thread, 128 thr)

    k_zero<<<(B / 4 + 255) / 256, 256>>>(B);
    k_qwhist<<<QB + HB, 128>>>(query, W, index, B, N, QB);
    k_scan<<<1, 256>>>(B);
    k_scatter<<<(N + 8 * 256 - 1) / (8 * 256), 256>>>(index, N);
    k_main<<<B, 256>>>(values, out, B);
}